// round 13
// baseline (speedup 1.0000x reference)
#include <cuda_runtime.h>
#include <cuda.h>
#include <cuda_fp16.h>
#include <math.h>
#include <stdint.h>
#include <dlfcn.h>

#define H     1024
#define MLPH  4096
#define EXPH  2048
#define NEXP  8
#define NTOK  4096

// tcgen05 is an "a"-suffix feature: real body only in arch-specific passes.
#if !defined(__CUDA_ARCH__) || defined(__CUDA_ARCH_FEAT_SM103_ALL) || defined(__CUDA_ARCH_FEAT_SM100_ALL) || defined(__CUDA_ARCH_SPECIFIC__)
#define TC_OK 1
#else
#define TC_OK 0
#endif

// ---------------- static device scratch ----------------
__device__ __half g_xn [(size_t)NTOK * H];
__device__ __half g_h1 [(size_t)NTOK * MLPH];
__device__ float  g_h  [(size_t)NTOK * H];
__device__ float  g_h2 [(size_t)NTOK * H];           // GEMM2 K-split partial
__device__ __half g_x2h[(size_t)NTOK * H];
__device__ __half g_he [(size_t)NEXP * NTOK * EXPH];
__device__ float  g_ye [(size_t)NEXP * NTOK * H];
__device__ float  g_ye2[(size_t)NEXP * NTOK * H];    // eGEMM2 K-split partial
__device__ float  g_zero[H];                          // zero bias (never written)
__device__ int    g_cnt[NEXP];
__device__ int    g_tok[NEXP * NTOK];
__device__ int    g_slot[2 * NTOK];
__device__ float  g_wgt[2 * NTOK];
// transposed fp16 weights: [N, K] K-major
__device__ __half g_w1t[(size_t)MLPH * H];
__device__ __half g_w2t[(size_t)H * MLPH];
__device__ __half g_e1t[(size_t)NEXP * EXPH * H];
__device__ __half g_e2t[(size_t)NEXP * H * EXPH];

// ---------------- PTX helpers ----------------
__device__ __forceinline__ uint32_t smem_u32(const void* p) {
    uint32_t a;
    asm("{ .reg .u64 t; cvta.to.shared.u64 t, %1; cvt.u32.u64 %0, t; }" : "=r"(a) : "l"(p));
    return a;
}
__device__ __forceinline__ uint32_t elect_one_pred() {
    uint32_t p;
    asm volatile("{\n\t.reg .pred q;\n\telect.sync _|q, 0xFFFFFFFF;\n\tselp.b32 %0, 1, 0, q;\n\t}" : "=r"(p));
    return p;
}
#define MBARRIER_INIT(addr, cnt) \
    asm volatile("mbarrier.init.shared.b64 [%0], %1;" :: "r"((uint32_t)(addr)), "r"((uint32_t)(cnt)) : "memory")
#define MBARRIER_EXPECT_TX(addr, bytes) \
    asm volatile("mbarrier.arrive.expect_tx.shared.b64 _, [%0], %1;" :: "r"((uint32_t)(addr)), "r"((uint32_t)(bytes)) : "memory")
#define MBARRIER_WAIT_PARITY(addr, par) do { \
    uint32_t _m = (uint32_t)(addr), _p = (uint32_t)(par), _d; \
    asm volatile("{\n\t.reg .pred p;\n\tmbarrier.try_wait.parity.acquire.cta.shared::cta.b64 p, [%1], %2;\n\tselp.b32 %0, 1, 0, p;\n\t}" \
        : "=r"(_d) : "r"(_m), "r"(_p) : "memory"); \
    if (!_d) { \
        asm volatile("{\n\t.reg .pred P1;\n\tWL_%=:\n\tmbarrier.try_wait.parity.acquire.cta.shared::cta.b64 P1, [%0], %1, 0x989680;\n\t@P1 bra.uni WD_%=;\n\tbra.uni WL_%=;\n\tWD_%=:\n\t}" \
            :: "r"(_m), "r"(_p) : "memory"); \
    } } while (0)
#define TMA_LOAD_3D(smemAddr, mapPtr, cx, cy, cz, mbar) \
    asm volatile("cp.async.bulk.tensor.3d.shared::cta.global.tile.mbarrier::complete_tx::bytes " \
        "[%0], [%1, {%2, %3, %4}], [%5];" \
        :: "r"((uint32_t)(smemAddr)), "l"(mapPtr), "r"((int)(cx)), "r"((int)(cy)), "r"((int)(cz)), \
           "r"((uint32_t)(mbar)) : "memory")

__device__ __forceinline__ void cpa16(uint32_t dst, const void* src, uint32_t sz) {
    asm volatile("cp.async.cg.shared.global [%0], [%1], 16, %2;"
        :: "r"(dst), "l"(src), "r"(sz) : "memory");
}
#define CP_COMMIT() asm volatile("cp.async.commit_group;" ::: "memory")
#define CP_WAIT1()  asm volatile("cp.async.wait_group 1;" ::: "memory")
#define CP_WAIT0()  asm volatile("cp.async.wait_group 0;" ::: "memory")

#if TC_OK
#define TCGEN05_ALLOC(saddr, n) \
    asm volatile("tcgen05.alloc.cta_group::1.sync.aligned.shared::cta.b32 [%0], %1;" :: "r"((uint32_t)(saddr)), "r"((uint32_t)(n)) : "memory")
#define TCGEN05_RELINQ() \
    asm volatile("tcgen05.relinquish_alloc_permit.cta_group::1.sync.aligned;")
#define TCGEN05_DEALLOC(taddr, n) \
    asm volatile("tcgen05.dealloc.cta_group::1.sync.aligned.b32 %0, %1;" :: "r"(taddr), "r"((uint32_t)(n)))
#define TCGEN05_COMMIT(mbar) \
    asm volatile("tcgen05.commit.cta_group::1.mbarrier::arrive::one.shared::cluster.b64 [%0];" :: "r"((uint32_t)(mbar)) : "memory")
#define TCGEN05_WAIT_LD()  asm volatile("tcgen05.wait::ld.sync.aligned;" ::: "memory")
#define TCGEN05_FENCE_AFTER()  asm volatile("tcgen05.fence::after_thread_sync;" ::: "memory")
#define TCGEN05_FENCE_BEFORE() asm volatile("tcgen05.fence::before_thread_sync;" ::: "memory")
#define TCGEN05_LD_X32(r, ta) \
    asm volatile("tcgen05.ld.sync.aligned.32x32b.x32.b32 " \
        "{%0, %1, %2, %3, %4, %5, %6, %7, %8, %9, %10, %11, %12, %13, %14, %15, " \
        " %16, %17, %18, %19, %20, %21, %22, %23, %24, %25, %26, %27, %28, %29, %30, %31}, [%32];" \
        : "=r"((r)[0]),  "=r"((r)[1]),  "=r"((r)[2]),  "=r"((r)[3]), \
          "=r"((r)[4]),  "=r"((r)[5]),  "=r"((r)[6]),  "=r"((r)[7]), \
          "=r"((r)[8]),  "=r"((r)[9]),  "=r"((r)[10]), "=r"((r)[11]), \
          "=r"((r)[12]), "=r"((r)[13]), "=r"((r)[14]), "=r"((r)[15]), \
          "=r"((r)[16]), "=r"((r)[17]), "=r"((r)[18]), "=r"((r)[19]), \
          "=r"((r)[20]), "=r"((r)[21]), "=r"((r)[22]), "=r"((r)[23]), \
          "=r"((r)[24]), "=r"((r)[25]), "=r"((r)[26]), "=r"((r)[27]), \
          "=r"((r)[28]), "=r"((r)[29]), "=r"((r)[30]), "=r"((r)[31]) \
        : "r"(ta))

__device__ __forceinline__ void mma_f16(uint32_t d, uint64_t ad, uint64_t bd, uint32_t idesc, bool acc) {
    uint32_t en = acc ? 1u : 0u, z = 0u;
    asm volatile("{\n\t.reg .pred p;\n\tsetp.ne.u32 p, %5, 0;\n\t"
        "tcgen05.mma.cta_group::1.kind::f16 [%0], %1, %2, %3, {%4,%4,%4,%4}, p;\n\t}"
        :: "r"(d), "l"(ad), "l"(bd), "r"(idesc), "r"(z), "r"(en) : "memory");
}
#endif // TC_OK

static __device__ __forceinline__ uint64_t make_desc(uint32_t addr) {
    // K-major SW128: layout=2, version=1, SBO=64, LBO=1
    uint64_t d = (uint64_t(2) << 61) | (uint64_t(1) << 46) | (uint64_t(64) << 32) | (uint64_t(1) << 16);
    return d | ((uint64_t)(addr >> 4) & 0x3FFF);
}
__device__ __forceinline__ uint32_t sw128(uint32_t o) { return o ^ ((o >> 3) & 0x70); }
__device__ __forceinline__ float gelu_exact(float x) {
    return 0.5f * x * (1.0f + erff(x * 0.7071067811865476f));
}
__device__ __forceinline__ float warp_sum(float v) {
    #pragma unroll
    for (int o = 16; o; o >>= 1) v += __shfl_xor_sync(0xffffffffu, v, o);
    return v;
}

template<bool B> struct OutSel;
template<> struct OutSel<true>  { using T = __half; };
template<> struct OutSel<false> { using T = float;  };

// ---------------- smem map (dynamic, 99328 B): 2-stage pipeline -----------------
// [0:4) tmem ptr  [64:96) mbarriers: full0,full1,em0,em1   (gather: em at +8,+16)
// A stage s: 1024  + s*16384  (128 rows x 64 k fp16, SW128)
// B stage s: 33792 + s*32768  (256 rows x 64 k fp16, SW128)
#define SMEM_BYTES 99328
#define STAGE_TX  ((64*128 + 64*256) * 2)   // 49152 B per stage

// idesc kind::f16: dtype F32=1 [4:5], fp16 A/B, N=256, M=128
#define IDESC_F16 ((1u << 4) | ((256u / 8) << 17) | ((128u / 16) << 24))

// ====== TMA GEMM: 128(M) x 256(N), K-stage 64, optional 2-way K-split ==========
// EPI: 0 = half(gelu(acc+bias)), 1 = acc+bias(+res on half 0), 2 = acc+bias
// KSPLIT: z encodes (expert, half); half 1 writes C1 with zero bias, K offset +K.
template<int EPI, bool EXPERT, bool KSPLIT>
__global__ void __launch_bounds__(256, 2)
tma_gemm(const __grid_constant__ CUtensorMap mA,
         const __grid_constant__ CUtensorMap mB,
         void* __restrict__ C0v, void* __restrict__ C1v, int ldc, long strideC,
         const float* __restrict__ bias0, const float* __restrict__ biasZ,
         int strideBias, const float* __restrict__ res,
         const int* __restrict__ cnt, int M0, int K) {
#if !TC_OK
    return;
#else
    using CT = typename OutSel<EPI == 0>::T;
    int zc = blockIdx.z;
    int e    = EXPERT ? (KSPLIT ? (zc >> 1) : zc) : 0;
    int half = KSPLIT ? (EXPERT ? (zc & 1) : zc) : 0;
    int kOff = half * K;
    int M = EXPERT ? cnt[e] : M0;
    int mBase = blockIdx.y * 128;
    if (mBase >= M) return;
    int colBase = blockIdx.x * 256;

    extern __shared__ char smem[];
    uint32_t sb = smem_u32(smem);
    int tid = threadIdx.x, wid = tid >> 5, lane = tid & 31;

    if (wid == 0) { TCGEN05_ALLOC(sb, 256); TCGEN05_RELINQ(); }
    if (tid == 0) {
        MBARRIER_INIT(sb + 64, 1);
        MBARRIER_INIT(sb + 72, 1);
        MBARRIER_INIT(sb + 80, 1);
        MBARRIER_INIT(sb + 88, 1);
    }
    __syncthreads();
    uint32_t tmem;
    asm volatile("ld.shared.b32 %0, [%1];" : "=r"(tmem) : "r"(sb));

    CT* C = (CT*)(half ? C1v : C0v) + (EXPERT ? (long)e * strideC : 0);
    const float* bias = half ? biasZ : (bias0 + (EXPERT ? e * strideBias : 0));

    const uint32_t aOff[2] = { 1024u, 1024u + 16384u };
    const uint32_t bOff[2] = { 33792u, 33792u + 32768u };
    uint64_t aDesc[2], bDesc[2];
    #pragma unroll
    for (int s = 0; s < 2; s++) { aDesc[s] = make_desc(sb + aOff[s]); bDesc[s] = make_desc(sb + bOff[s]); }

    int T = K / 64;

    if (wid == 0) {
        bool lead = elect_one_pred() != 0;
        if (lead) {
            #pragma unroll
            for (int s = 0; s < 2; s++) {
                MBARRIER_EXPECT_TX(sb + 64 + s * 8, STAGE_TX);
                TMA_LOAD_3D(sb + aOff[s], &mA, kOff + s * 64, mBase,   e, sb + 64 + s * 8);
                TMA_LOAD_3D(sb + bOff[s], &mB, kOff + s * 64, colBase, e, sb + 64 + s * 8);
            }
        }
        int phF[2] = {0, 0}, phE[2] = {0, 0};
        for (int t = 0; t < T; t++) {
            int b = t & 1;
            MBARRIER_WAIT_PARITY(sb + 64 + b * 8, phF[b]); phF[b] ^= 1;
            if (lead) {
                #pragma unroll
                for (int k = 0; k < 4; k++)
                    mma_f16(tmem, aDesc[b] + k * 2, bDesc[b] + k * 2, IDESC_F16, (t > 0) || (k > 0));
                TCGEN05_COMMIT(sb + 80 + b * 8);
            }
            if (t + 2 < T) {
                MBARRIER_WAIT_PARITY(sb + 80 + b * 8, phE[b]); phE[b] ^= 1;
                if (lead) {
                    int kx = kOff + (t + 2) * 64;
                    MBARRIER_EXPECT_TX(sb + 64 + b * 8, STAGE_TX);
                    TMA_LOAD_3D(sb + aOff[b], &mA, kx, mBase,   e, sb + 64 + b * 8);
                    TMA_LOAD_3D(sb + bOff[b], &mB, kx, colBase, e, sb + 64 + b * 8);
                }
            }
        }
        int lb = (T - 1) & 1;
        MBARRIER_WAIT_PARITY(sb + 80 + lb * 8, phE[lb]);
    }
    __syncthreads();
    TCGEN05_FENCE_AFTER();

    int wq = wid & 3, wh = wid >> 2;
    int row = mBase + wq * 32 + lane;
    bool rOk = row < M;
    CT* crow = C + (long)row * ldc;
    const float* rrow = res + (long)row * ldc;
    bool addRes = (EPI == 1) && (!KSPLIT || half == 0);
    #pragma unroll
    for (int c = 0; c < 4; c++) {
        int col0 = wh * 128 + c * 32;
        uint32_t r[32];
        TCGEN05_LD_X32(r, tmem + col0);
        TCGEN05_WAIT_LD();
        if (rOk) {
            #pragma unroll
            for (int j = 0; j < 32; j += 4) {
                int g = colBase + col0 + j;
                float4 o;
                o.x = __uint_as_float(r[j + 0]) + bias[g + 0];
                o.y = __uint_as_float(r[j + 1]) + bias[g + 1];
                o.z = __uint_as_float(r[j + 2]) + bias[g + 2];
                o.w = __uint_as_float(r[j + 3]) + bias[g + 3];
                if (EPI == 0) {
                    __half2 h0 = __floats2half2_rn(gelu_exact(o.x), gelu_exact(o.y));
                    __half2 h1v = __floats2half2_rn(gelu_exact(o.z), gelu_exact(o.w));
                    __half2* hp = (__half2*)((__half*)crow + g);
                    hp[0] = h0; hp[1] = h1v;
                } else {
                    if (addRes) {
                        o.x += rrow[g + 0]; o.y += rrow[g + 1];
                        o.z += rrow[g + 2]; o.w += rrow[g + 3];
                    }
                    *(float4*)((float*)crow + g) = o;
                }
            }
        }
    }
    TCGEN05_FENCE_BEFORE();
    __syncthreads();
    if (wid == 0) TCGEN05_DEALLOC(tmem, 256);
#endif // TC_OK
}

// ============ cp.async-fed gather GEMM (expert GEMM1), 2-stage (R6/R7-proven) ===
__global__ void __launch_bounds__(256, 2)
gather_gemm(const __half* __restrict__ A0, int lda,
            const __half* __restrict__ B0, int ldb, long strideB,
            __half* __restrict__ C0, int ldc, long strideC,
            const float* __restrict__ bias0, int strideBias,
            const int* __restrict__ tok, int tokStride,
            const int* __restrict__ cnt, int K) {
#if !TC_OK
    return;
#else
    int e = blockIdx.z;
    int M = cnt[e];
    int mBase = blockIdx.y * 128;
    if (mBase >= M) return;
    int colBase = blockIdx.x * 256;

    extern __shared__ char smem[];
    uint32_t sb = smem_u32(smem);
    int tid = threadIdx.x, wid = tid >> 5, lane = tid & 31;

    if (wid == 0) { TCGEN05_ALLOC(sb, 256); TCGEN05_RELINQ(); }
    if (tid == 0) { MBARRIER_INIT(sb + 8, 1); MBARRIER_INIT(sb + 16, 1); }
    __syncthreads();
    uint32_t tmem;
    asm volatile("ld.shared.b32 %0, [%1];" : "=r"(tmem) : "r"(sb));

    const __half* B = B0 + (long)e * strideB;
    __half*       C = C0 + (long)e * strideC;
    const float* bias = bias0 + e * strideBias;

    const __half* aPtr[4]; uint32_t aSz[4]; uint32_t aSoff[4];
    #pragma unroll
    for (int i = 0; i < 4; i++) {
        int idx = tid + 256 * i;
        int r = idx >> 3, kq = idx & 7;
        int grow = mBase + r;
        bool ok = grow < M;
        long rr = ok ? (long)tok[e * tokStride + grow] : 0;
        aPtr[i] = A0 + rr * (long)lda + kq * 8;
        aSz[i] = ok ? 16u : 0u;
        aSoff[i] = sw128((uint32_t)(r * 128 + kq * 16));
    }
    const __half* bPtr[8]; uint32_t bSoff[8];
    #pragma unroll
    for (int i = 0; i < 8; i++) {
        int idx = tid + 256 * i;
        int r = idx >> 3, kq = idx & 7;
        bPtr[i] = B + (long)(colBase + r) * ldb + kq * 8;
        bSoff[i] = sw128((uint32_t)(r * 128 + kq * 16));
    }

    const uint32_t aOff[2] = { 1024u, 1024u + 16384u };
    const uint32_t bOff[2] = { 33792u, 33792u + 32768u };
    uint64_t aDesc[2], bDesc[2];
    #pragma unroll
    for (int s = 0; s < 2; s++) { aDesc[s] = make_desc(sb + aOff[s]); bDesc[s] = make_desc(sb + bOff[s]); }

    #pragma unroll
    for (int i = 0; i < 4; i++) cpa16(sb + aOff[0] + aSoff[i], aPtr[i], aSz[i]);
    #pragma unroll
    for (int i = 0; i < 8; i++) cpa16(sb + bOff[0] + bSoff[i], bPtr[i], 16u);
    CP_COMMIT();

    int T = K / 64;
    int ph0 = 0, ph1 = 0;
    for (int t = 0; t < T; t++) {
        int b = t & 1;
        if (t + 1 < T) {
            int s = b ^ 1;
            if (t >= 1) {
                if (s) { MBARRIER_WAIT_PARITY(sb + 16, ph1); ph1 ^= 1; }
                else   { MBARRIER_WAIT_PARITY(sb + 8,  ph0); ph0 ^= 1; }
            }
            int off = (t + 1) * 64;
            #pragma unroll
            for (int i = 0; i < 4; i++) cpa16(sb + aOff[s] + aSoff[i], aPtr[i] + off, aSz[i]);
            #pragma unroll
            for (int i = 0; i < 8; i++) cpa16(sb + bOff[s] + bSoff[i], bPtr[i] + off, 16u);
            CP_COMMIT();
            CP_WAIT1();
        } else {
            CP_WAIT0();
        }
        asm volatile("fence.proxy.async.shared::cta;" ::: "memory");
        __syncthreads();
        if (wid == 0 && elect_one_pred()) {
            #pragma unroll
            for (int k = 0; k < 4; k++)
                mma_f16(tmem, aDesc[b] + k * 2, bDesc[b] + k * 2, IDESC_F16, (t > 0) || (k > 0));
            TCGEN05_COMMIT(sb + 8 + b * 8);
        }
    }
    {
        int lb = (T - 1) & 1;
        if (lb) { MBARRIER_WAIT_PARITY(sb + 16, ph1); }
        else    { MBARRIER_WAIT_PARITY(sb + 8,  ph0); }
    }
    TCGEN05_FENCE_AFTER();

    int wq = wid & 3, wh = wid >> 2;
    int row = mBase + wq * 32 + lane;
    bool rOk = row < M;
    __half* crow = C + (long)row * ldc;
    #pragma unroll
    for (int c = 0; c < 4; c++) {
        int col0 = wh * 128 + c * 32;
        uint32_t r[32];
        TCGEN05_LD_X32(r, tmem + col0);
        TCGEN05_WAIT_LD();
        if (rOk) {
            #pragma unroll
            for (int j = 0; j < 32; j += 4) {
                int g = colBase + col0 + j;
                float vx = __uint_as_float(r[j + 0]) + bias[g + 0];
                float vy = __uint_as_float(r[j + 1]) + bias[g + 1];
                float vz = __uint_as_float(r[j + 2]) + bias[g + 2];
                float vw = __uint_as_float(r[j + 3]) + bias[g + 3];
                __half2* hp = (__half2*)(crow + g);
                hp[0] = __floats2half2_rn(gelu_exact(vx), gelu_exact(vy));
                hp[1] = __floats2half2_rn(gelu_exact(vz), gelu_exact(vw));
            }
        }
    }
    TCGEN05_FENCE_BEFORE();
    __syncthreads();
    if (wid == 0) TCGEN05_DEALLOC(tmem, 256);
#endif // TC_OK
}

// ---------------- fused weight transpose (also resets cnt) ----------------
__global__ void transpose_all(const float* __restrict__ w1, __half* __restrict__ w1t,
                              const float* __restrict__ w2, __half* __restrict__ w2t,
                              const float* __restrict__ e1, __half* __restrict__ e1t,
                              const float* __restrict__ e2, __half* __restrict__ e2t,
                              int* __restrict__ cnt) {
    if (blockIdx.x == 0 && threadIdx.x < NEXP) cnt[threadIdx.x] = 0;
    int id = blockIdx.x;
    const float* in; __half* outp; int R, C;
    if (id < 4096)        { in = w1; outp = w1t; R = H;    C = MLPH; }
    else if (id < 8192)   { id -= 4096; in = w2; outp = w2t; R = MLPH; C = H; }
    else if (id < 24576)  { id -= 8192; int ex = id >> 11; id &= 2047;
                            in = e1 + (size_t)ex * H * EXPH; outp = e1t + (size_t)ex * H * EXPH;
                            R = H; C = EXPH; }
    else                  { id -= 24576; int ex = id >> 11; id &= 2047;
                            in = e2 + (size_t)ex * EXPH * H; outp = e2t + (size_t)ex * EXPH * H;
                            R = EXPH; C = H; }
    int ctiles = C >> 5;
    int r0 = (id / ctiles) << 5, c0 = (id % ctiles) << 5;

    __shared__ float tile[32][33];
    int tid = threadIdx.x;
    int row = tid >> 3, q = tid & 7;
    float4 v = *(const float4*)&in[(size_t)(r0 + row) * C + c0 + q * 4];
    tile[row][q * 4 + 0] = v.x; tile[row][q * 4 + 1] = v.y;
    tile[row][q * 4 + 2] = v.z; tile[row][q * 4 + 3] = v.w;
    __syncthreads();
    int h2 = tid & 15, ccb = tid >> 4;
    #pragma unroll
    for (int p = 0; p < 2; p++) {
        int cc = ccb + p * 16;
        __half2 hv = __floats2half2_rn(tile[h2 * 2][cc], tile[h2 * 2 + 1][cc]);
        *(__half2*)&outp[(size_t)(c0 + cc) * R + r0 + h2 * 2] = hv;
    }
}

// ---------------- warp-per-token LayerNorm (+in2 partial, +optional router) -----
template<int ADDSELF, int DOROUTER>
__global__ void __launch_bounds__(128)
ln_warp(const float* __restrict__ in, const float* __restrict__ in2,
        const float* __restrict__ g, const float* __restrict__ b,
        __half* __restrict__ outH,
        const float* __restrict__ rw, int* __restrict__ cnt,
        int* __restrict__ tok, int* __restrict__ slot,
        float* __restrict__ wgt, int NT) {
    int warp = threadIdx.x >> 5, lane = threadIdx.x & 31;
    int n = blockIdx.x * 4 + warp;
    const float4* inr  = (const float4*)(in + (long)n * H);
    const float4* in2r = in2 ? (const float4*)(in2 + (long)n * H) : nullptr;
    const float4* g4  = (const float4*)g;
    const float4* b4  = (const float4*)b;

    float4 v[8];
    float s = 0.f;
    #pragma unroll
    for (int j = 0; j < 8; j++) {
        v[j] = inr[j * 32 + lane];
        if (in2r) {
            float4 p = in2r[j * 32 + lane];
            v[j].x += p.x; v[j].y += p.y; v[j].z += p.z; v[j].w += p.w;
        }
        s += v[j].x + v[j].y + v[j].z + v[j].w;
    }
    float mean = warp_sum(s) * (1.0f / H);
    float vs = 0.f;
    #pragma unroll
    for (int j = 0; j < 8; j++) {
        float dx = v[j].x - mean, dy = v[j].y - mean, dz = v[j].z - mean, dw = v[j].w - mean;
        vs += dx * dx + dy * dy + dz * dz + dw * dw;
    }
    float rs = rsqrtf(warp_sum(vs) * (1.0f / H) + 1e-5f);

    __half* outRow = outH + (long)n * H;
    #pragma unroll
    for (int j = 0; j < 8; j++) {
        int idx = j * 32 + lane;
        float4 gv = g4[idx], bv = b4[idx];
        float4 o;
        o.x = (v[j].x - mean) * rs * gv.x + bv.x;
        o.y = (v[j].y - mean) * rs * gv.y + bv.y;
        o.z = (v[j].z - mean) * rs * gv.z + bv.z;
        o.w = (v[j].w - mean) * rs * gv.w + bv.w;
        if (ADDSELF) { o.x += v[j].x; o.y += v[j].y; o.z += v[j].z; o.w += v[j].w; }
        v[j] = o;   // keep fp32 for router
        __half2 h01 = __floats2half2_rn(o.x, o.y);
        __half2 h23 = __floats2half2_rn(o.z, o.w);
        uint2 u = make_uint2(*(unsigned*)&h01, *(unsigned*)&h23);
        *(uint2*)(outRow + idx * 4) = u;
    }

    if (DOROUTER) {
        float acc[NEXP];
        #pragma unroll
        for (int e = 0; e < NEXP; e++) acc[e] = 0.f;
        #pragma unroll
        for (int j = 0; j < 8; j++) {
            int h0 = (j * 32 + lane) * 4;
            float xv[4] = { v[j].x, v[j].y, v[j].z, v[j].w };
            #pragma unroll
            for (int k = 0; k < 4; k++) {
                const float4* r = (const float4*)&rw[(h0 + k) * NEXP];
                float4 r0 = r[0], r1 = r[1];
                float x = xv[k];
                acc[0] += x * r0.x; acc[1] += x * r0.y; acc[2] += x * r0.z; acc[3] += x * r0.w;
                acc[4] += x * r1.x; acc[5] += x * r1.y; acc[6] += x * r1.z; acc[7] += x * r1.w;
            }
        }
        #pragma unroll
        for (int e = 0; e < NEXP; e++) acc[e] = warp_sum(acc[e]);
        if (lane == 0) {
            int i1 = 0;
            #pragma unroll
            for (int e = 1; e < NEXP; e++) if (acc[e] > acc[i1]) i1 = e;
            int i2 = (i1 == 0) ? 1 : 0;
            #pragma unroll
            for (int e = 0; e < NEXP; e++) { if (e == i1 || e == i2) continue; if (acc[e] > acc[i2]) i2 = e; }
            float d  = expf(acc[i2] - acc[i1]);
            float w1 = 1.0f / (1.0f + d);
            float w2 = d / (1.0f + d);
            int p1 = atomicAdd(&cnt[i1], 1);
            int p2 = atomicAdd(&cnt[i2], 1);
            tok[i1 * NT + p1] = n;
            tok[i2 * NT + p2] = n;
            slot[2*n]   = i1 * NT + p1;  wgt[2*n]   = w1;
            slot[2*n+1] = i2 * NT + p2;  wgt[2*n+1] = w2;
        }
    }
}

// ---------------- warp-per-token combine (two partials) + final LN --------------
__global__ void __launch_bounds__(128)
combine_ln_warp(const float* __restrict__ ye, const float* __restrict__ ye2,
                const int* __restrict__ slot, const float* __restrict__ wgt,
                const float* __restrict__ g, const float* __restrict__ b,
                float* __restrict__ out) {
    int warp = threadIdx.x >> 5, lane = threadIdx.x & 31;
    int n = blockIdx.x * 4 + warp;
    int s0 = slot[2*n], s1 = slot[2*n+1];
    float w0 = wgt[2*n], w1 = wgt[2*n+1];
    const float4* y0a = (const float4*)(ye  + (long)s0 * H);
    const float4* y0b = (const float4*)(ye2 + (long)s0 * H);
    const float4* y1a = (const float4*)(ye  + (long)s1 * H);
    const float4* y1b = (const float4*)(ye2 + (long)s1 * H);
    const float4* g4  = (const float4*)g;
    const float4* b4  = (const float4*)b;

    float4 v[8];
    float s = 0.f;
    #pragma unroll
    for (int j = 0; j < 8; j++) {
        int idx = j * 32 + lane;
        float4 a0 = y0a[idx], a1 = y0b[idx], c0 = y1a[idx], c1 = y1b[idx];
        float4 t;
        t.x = w0 * (a0.x + a1.x) + w1 * (c0.x + c1.x);
        t.y = w0 * (a0.y + a1.y) + w1 * (c0.y + c1.y);
        t.z = w0 * (a0.z + a1.z) + w1 * (c0.z + c1.z);
        t.w = w0 * (a0.w + a1.w) + w1 * (c0.w + c1.w);
        v[j] = t;
        s += t.x + t.y + t.z + t.w;
    }
    float mean = warp_sum(s) * (1.0f / H);
    float vs = 0.f;
    #pragma unroll
    for (int j = 0; j < 8; j++) {
        float dx = v[j].x - mean, dy = v[j].y - mean, dz = v[j].z - mean, dw = v[j].w - mean;
        vs += dx * dx + dy * dy + dz * dz + dw * dw;
    }
    float rs = rsqrtf(warp_sum(vs) * (1.0f / H) + 1e-5f);

    float4* outRow = (float4*)(out + (long)n * H);
    #pragma unroll
    for (int j = 0; j < 8; j++) {
        int idx = j * 32 + lane;
        float4 gv = g4[idx], bv = b4[idx];
        float4 o;
        o.x = (v[j].x - mean) * rs * gv.x + bv.x;
        o.y = (v[j].y - mean) * rs * gv.y + bv.y;
        o.z = (v[j].z - mean) * rs * gv.z + bv.z;
        o.w = (v[j].w - mean) * rs * gv.w + bv.w;
        outRow[idx] = o;
    }
}

__global__ void aux_kernel(const int* __restrict__ cnt, float* __restrict__ out,
                           long auxIdx, float invTotal) {
    float a = 0.f;
    #pragma unroll
    for (int e = 0; e < NEXP; e++) {
        float load = (float)cnt[e] * invTotal;
        a += load * logf(load + 1e-9f);
    }
    out[auxIdx] = 0.01f * a;
}

// ---------------- host: tensormap builder via dlopen ----------------
typedef CUresult (*EncodeFn)(CUtensorMap*, CUtensorMapDataType, cuuint32_t, void*,
                             const cuuint64_t*, const cuuint64_t*, const cuuint32_t*,
                             const cuuint32_t*, CUtensorMapInterleave, CUtensorMapSwizzle,
                             CUtensorMapL2promotion, CUtensorMapFloatOOBfill);

static void make_map_h(EncodeFn enc, CUtensorMap* m, void* ptr,
                       uint64_t d0, uint64_t d1, uint64_t d2, uint32_t box1) {
    cuuint64_t dims[3]    = { d0, d1, d2 };
    cuuint64_t strides[2] = { d0 * 2, d0 * d1 * 2 };
    cuuint32_t box[3]     = { 64u, box1, 1u };
    cuuint32_t es[3]      = { 1u, 1u, 1u };
    enc(m, CU_TENSOR_MAP_DATA_TYPE_FLOAT16, 3, ptr, dims, strides, box, es,
        CU_TENSOR_MAP_INTERLEAVE_NONE, CU_TENSOR_MAP_SWIZZLE_128B,
        CU_TENSOR_MAP_L2_PROMOTION_L2_128B, CU_TENSOR_MAP_FLOAT_OOB_FILL_NONE);
}

// ---------------- launch ----------------
extern "C" void kernel_launch(void* const* d_in, const int* in_sizes, int n_in,
                              void* d_out, int out_size) {
    const float* x    = (const float*)d_in[0];
    const float* ln1g = (const float*)d_in[1];
    const float* ln1b = (const float*)d_in[2];
    const float* ln2g = (const float*)d_in[3];
    const float* ln2b = (const float*)d_in[4];
    const float* w1   = (const float*)d_in[5];
    const float* b1   = (const float*)d_in[6];
    const float* w2   = (const float*)d_in[7];
    const float* b2   = (const float*)d_in[8];
    const float* rw   = (const float*)d_in[9];
    const float* ew1  = (const float*)d_in[10];
    const float* eb1  = (const float*)d_in[11];
    const float* ew2  = (const float*)d_in[12];
    const float* eb2  = (const float*)d_in[13];
    const float* lnfg = (const float*)d_in[14];
    const float* lnfb = (const float*)d_in[15];
    float* out = (float*)d_out;

    int NT = in_sizes[0] / H;   // 4096

    __half *xn, *h1, *x2h, *he, *w1t, *w2t, *e1t, *e2t;
    float *hh, *h2, *ye, *ye2, *zero, *wgt;
    int *cnt, *tok, *slot;
    cudaGetSymbolAddress((void**)&xn,   g_xn);
    cudaGetSymbolAddress((void**)&h1,   g_h1);
    cudaGetSymbolAddress((void**)&hh,   g_h);
    cudaGetSymbolAddress((void**)&h2,   g_h2);
    cudaGetSymbolAddress((void**)&x2h,  g_x2h);
    cudaGetSymbolAddress((void**)&he,   g_he);
    cudaGetSymbolAddress((void**)&ye,   g_ye);
    cudaGetSymbolAddress((void**)&ye2,  g_ye2);
    cudaGetSymbolAddress((void**)&zero, g_zero);
    cudaGetSymbolAddress((void**)&wgt,  g_wgt);
    cudaGetSymbolAddress((void**)&cnt,  g_cnt);
    cudaGetSymbolAddress((void**)&tok,  g_tok);
    cudaGetSymbolAddress((void**)&slot, g_slot);
    cudaGetSymbolAddress((void**)&w1t,  g_w1t);
    cudaGetSymbolAddress((void**)&w2t,  g_w2t);
    cudaGetSymbolAddress((void**)&e1t,  g_e1t);
    cudaGetSymbolAddress((void**)&e2t,  g_e2t);

    // tensormaps (host-built; deterministic; baked into graph as kernel params)
    void* hcu = dlopen("libcuda.so.1", RTLD_LAZY | RTLD_GLOBAL);
    if (!hcu) hcu = dlopen("libcuda.so", RTLD_LAZY | RTLD_GLOBAL);
    EncodeFn enc = hcu ? (EncodeFn)dlsym(hcu, "cuTensorMapEncodeTiled") : nullptr;
    CUtensorMap mXn, mW1, mH1, mW2, mHe, mE2;
    make_map_h(enc, &mXn, xn,  H,    (uint64_t)NT, 1,    128);
    make_map_h(enc, &mW1, w1t, H,    MLPH,         1,    256);
    make_map_h(enc, &mH1, h1,  MLPH, (uint64_t)NT, 1,    128);
    make_map_h(enc, &mW2, w2t, MLPH, H,            1,    256);
    make_map_h(enc, &mHe, he,  EXPH, (uint64_t)NT, NEXP, 128);
    make_map_h(enc, &mE2, e2t, EXPH, H,            NEXP, 256);

    cudaFuncSetAttribute(tma_gemm<0, false, false>, cudaFuncAttributeMaxDynamicSharedMemorySize, SMEM_BYTES);
    cudaFuncSetAttribute(tma_gemm<1, false, true >, cudaFuncAttributeMaxDynamicSharedMemorySize, SMEM_BYTES);
    cudaFuncSetAttribute(tma_gemm<2, true,  true >, cudaFuncAttributeMaxDynamicSharedMemorySize, SMEM_BYTES);
    cudaFuncSetAttribute(gather_gemm,               cudaFuncAttributeMaxDynamicSharedMemorySize, SMEM_BYTES);

    // fused weight transpose + fp16 convert (+cnt reset) — ONE launch
    transpose_all<<<40960, 256>>>(w1, w1t, w2, w2t, ew1, e1t, ew2, e2t, cnt);

    // ResMLP block
    ln_warp<0, 0><<<NT / 4, 128>>>(x, nullptr, ln1g, ln1b, xn,
                                   nullptr, nullptr, nullptr, nullptr, nullptr, NT);
    tma_gemm<0, false, false><<<dim3(MLPH/256, NT/128), 256, SMEM_BYTES>>>(
        mXn, mW1, h1, nullptr, MLPH, 0, b1, nullptr, 0, nullptr, nullptr, NT, H);
    // GEMM2: 2-way K-split (z = half), partials hh + h2
    tma_gemm<1, false, true><<<dim3(H/256, NT/128, 2), 256, SMEM_BYTES>>>(
        mH1, mW2, hh, h2, H, 0, b2, zero, 0, x, nullptr, NT, MLPH / 2);

    // LN2 (sums partials) + fused router (exact fp32 logits)
    ln_warp<1, 1><<<NT / 4, 128>>>(hh, h2, ln2g, ln2b, x2h,
                                   rw, cnt, tok, slot, wgt, NT);

    // MoE
    gather_gemm<<<dim3(EXPH/256, NT/128, NEXP), 256, SMEM_BYTES>>>(
        x2h, H,  e1t, H, (long)EXPH * H,  he, EXPH, (long)NT * EXPH,
        eb1, EXPH, tok, NT, cnt, H);
    // eGEMM2: 2-way K-split (z = e*2+half), partials ye + ye2
    tma_gemm<2, true, true><<<dim3(H/256, NT/128, NEXP * 2), 256, SMEM_BYTES>>>(
        mHe, mE2, ye, ye2, H, (long)NT * H, eb2, zero, H, nullptr, cnt, NT, EXPH / 2);

    // combine (sums partials) + final LN + aux
    combine_ln_warp<<<NT / 4, 128>>>(ye, ye2, slot, wgt, lnfg, lnfb, out);
    if (out_size > NT * H)
        aux_kernel<<<1, 1>>>(cnt, out, (long)NT * H, 1.0f / (2.0f * NT));
}

// round 15
// speedup vs baseline: 1.0486x; 1.0486x over previous
#include <cuda_runtime.h>
#include <cuda.h>
#include <cuda_fp16.h>
#include <math.h>
#include <stdint.h>
#include <dlfcn.h>

#define H     1024
#define MLPH  4096
#define EXPH  2048
#define NEXP  8
#define NTOK  4096

// tcgen05 is an "a"-suffix feature: real body only in arch-specific passes.
#if !defined(__CUDA_ARCH__) || defined(__CUDA_ARCH_FEAT_SM103_ALL) || defined(__CUDA_ARCH_FEAT_SM100_ALL) || defined(__CUDA_ARCH_SPECIFIC__)
#define TC_OK 1
#else
#define TC_OK 0
#endif

// ---------------- static device scratch ----------------
__device__ __half g_xn [(size_t)NTOK * H];
__device__ __half g_h1 [(size_t)NTOK * MLPH];
__device__ float  g_h  [(size_t)NTOK * H];
__device__ __half g_x2h[(size_t)NTOK * H];
__device__ __half g_he [(size_t)NEXP * NTOK * EXPH];
__device__ float  g_ye [(size_t)NEXP * NTOK * H];
__device__ int    g_cnt[NEXP];
__device__ int    g_tok[NEXP * NTOK];
__device__ int    g_slot[2 * NTOK];
__device__ float  g_wgt[2 * NTOK];
// transposed fp16 weights: [N, K] K-major
__device__ __half g_w1t[(size_t)MLPH * H];
__device__ __half g_w2t[(size_t)H * MLPH];
__device__ __half g_e1t[(size_t)NEXP * EXPH * H];
__device__ __half g_e2t[(size_t)NEXP * H * EXPH];

// ---------------- PTX helpers ----------------
__device__ __forceinline__ uint32_t smem_u32(const void* p) {
    uint32_t a;
    asm("{ .reg .u64 t; cvta.to.shared.u64 t, %1; cvt.u32.u64 %0, t; }" : "=r"(a) : "l"(p));
    return a;
}
__device__ __forceinline__ uint32_t elect_one_pred() {
    uint32_t p;
    asm volatile("{\n\t.reg .pred q;\n\telect.sync _|q, 0xFFFFFFFF;\n\tselp.b32 %0, 1, 0, q;\n\t}" : "=r"(p));
    return p;
}
#define MBARRIER_INIT(addr, cnt) \
    asm volatile("mbarrier.init.shared.b64 [%0], %1;" :: "r"((uint32_t)(addr)), "r"((uint32_t)(cnt)) : "memory")
#define MBARRIER_EXPECT_TX(addr, bytes) \
    asm volatile("mbarrier.arrive.expect_tx.shared.b64 _, [%0], %1;" :: "r"((uint32_t)(addr)), "r"((uint32_t)(bytes)) : "memory")
#define MBARRIER_WAIT_PARITY(addr, par) do { \
    uint32_t _m = (uint32_t)(addr), _p = (uint32_t)(par), _d; \
    asm volatile("{\n\t.reg .pred p;\n\tmbarrier.try_wait.parity.acquire.cta.shared::cta.b64 p, [%1], %2;\n\tselp.b32 %0, 1, 0, p;\n\t}" \
        : "=r"(_d) : "r"(_m), "r"(_p) : "memory"); \
    if (!_d) { \
        asm volatile("{\n\t.reg .pred P1;\n\tWL_%=:\n\tmbarrier.try_wait.parity.acquire.cta.shared::cta.b64 P1, [%0], %1, 0x989680;\n\t@P1 bra.uni WD_%=;\n\tbra.uni WL_%=;\n\tWD_%=:\n\t}" \
            :: "r"(_m), "r"(_p) : "memory"); \
    } } while (0)
#define TMA_LOAD_3D(smemAddr, mapPtr, cx, cy, cz, mbar) \
    asm volatile("cp.async.bulk.tensor.3d.shared::cta.global.tile.mbarrier::complete_tx::bytes " \
        "[%0], [%1, {%2, %3, %4}], [%5];" \
        :: "r"((uint32_t)(smemAddr)), "l"(mapPtr), "r"((int)(cx)), "r"((int)(cy)), "r"((int)(cz)), \
           "r"((uint32_t)(mbar)) : "memory")
// cg2 TMA: both CTAs execute; complete_tx routed to leader CTA's barrier (bit 24 cleared)
#define TMA_LOAD_3D_CG2(smemAddr, mapPtr, cx, cy, cz, mbar) \
    asm volatile("{\n\t.reg .b32 lb;\n\tand.b32 lb, %5, 0xFEFFFFFF;\n\t" \
        "cp.async.bulk.tensor.3d.cta_group::2.shared::cluster.global.tile.mbarrier::complete_tx::bytes " \
        "[%0], [%1, {%2, %3, %4}], [lb];\n\t}" \
        :: "r"((uint32_t)(smemAddr)), "l"(mapPtr), "r"((int)(cx)), "r"((int)(cy)), "r"((int)(cz)), \
           "r"((uint32_t)(mbar)) : "memory")
#define CLUSTER_SYNC() do { \
    asm volatile("barrier.cluster.arrive.aligned;" ::: "memory"); \
    asm volatile("barrier.cluster.wait.aligned;" ::: "memory"); } while (0)

__device__ __forceinline__ void cpa16(uint32_t dst, const void* src, uint32_t sz) {
    asm volatile("cp.async.cg.shared.global [%0], [%1], 16, %2;"
        :: "r"(dst), "l"(src), "r"(sz) : "memory");
}
#define CP_COMMIT() asm volatile("cp.async.commit_group;" ::: "memory")
#define CP_WAIT1()  asm volatile("cp.async.wait_group 1;" ::: "memory")
#define CP_WAIT0()  asm volatile("cp.async.wait_group 0;" ::: "memory")

#if TC_OK
#define TCGEN05_ALLOC(saddr, n) \
    asm volatile("tcgen05.alloc.cta_group::1.sync.aligned.shared::cta.b32 [%0], %1;" :: "r"((uint32_t)(saddr)), "r"((uint32_t)(n)) : "memory")
#define TCGEN05_RELINQ() \
    asm volatile("tcgen05.relinquish_alloc_permit.cta_group::1.sync.aligned;")
#define TCGEN05_DEALLOC(taddr, n) \
    asm volatile("tcgen05.dealloc.cta_group::1.sync.aligned.b32 %0, %1;" :: "r"(taddr), "r"((uint32_t)(n)))
#define TCGEN05_ALLOC_CG2(saddr, n) \
    asm volatile("tcgen05.alloc.cta_group::2.sync.aligned.shared::cta.b32 [%0], %1;" :: "r"((uint32_t)(saddr)), "r"((uint32_t)(n)) : "memory")
#define TCGEN05_RELINQ_CG2() \
    asm volatile("tcgen05.relinquish_alloc_permit.cta_group::2.sync.aligned;")
#define TCGEN05_DEALLOC_CG2(taddr, n) \
    asm volatile("tcgen05.dealloc.cta_group::2.sync.aligned.b32 %0, %1;" :: "r"(taddr), "r"((uint32_t)(n)))
#define TCGEN05_COMMIT(mbar) \
    asm volatile("tcgen05.commit.cta_group::1.mbarrier::arrive::one.shared::cluster.b64 [%0];" :: "r"((uint32_t)(mbar)) : "memory")
#define TCGEN05_COMMIT_MC_CG2(mbar, mask) \
    asm volatile("tcgen05.commit.cta_group::2.mbarrier::arrive::one.shared::cluster.multicast::cluster.b64 [%0], %1;" \
        :: "r"((uint32_t)(mbar)), "h"((uint16_t)(mask)) : "memory")
#define TCGEN05_WAIT_LD()  asm volatile("tcgen05.wait::ld.sync.aligned;" ::: "memory")
#define TCGEN05_FENCE_AFTER()  asm volatile("tcgen05.fence::after_thread_sync;" ::: "memory")
#define TCGEN05_FENCE_BEFORE() asm volatile("tcgen05.fence::before_thread_sync;" ::: "memory")
#define TCGEN05_LD_X32(r, ta) \
    asm volatile("tcgen05.ld.sync.aligned.32x32b.x32.b32 " \
        "{%0, %1, %2, %3, %4, %5, %6, %7, %8, %9, %10, %11, %12, %13, %14, %15, " \
        " %16, %17, %18, %19, %20, %21, %22, %23, %24, %25, %26, %27, %28, %29, %30, %31}, [%32];" \
        : "=r"((r)[0]),  "=r"((r)[1]),  "=r"((r)[2]),  "=r"((r)[3]), \
          "=r"((r)[4]),  "=r"((r)[5]),  "=r"((r)[6]),  "=r"((r)[7]), \
          "=r"((r)[8]),  "=r"((r)[9]),  "=r"((r)[10]), "=r"((r)[11]), \
          "=r"((r)[12]), "=r"((r)[13]), "=r"((r)[14]), "=r"((r)[15]), \
          "=r"((r)[16]), "=r"((r)[17]), "=r"((r)[18]), "=r"((r)[19]), \
          "=r"((r)[20]), "=r"((r)[21]), "=r"((r)[22]), "=r"((r)[23]), \
          "=r"((r)[24]), "=r"((r)[25]), "=r"((r)[26]), "=r"((r)[27]), \
          "=r"((r)[28]), "=r"((r)[29]), "=r"((r)[30]), "=r"((r)[31]) \
        : "r"(ta))

__device__ __forceinline__ void mma_f16(uint32_t d, uint64_t ad, uint64_t bd, uint32_t idesc, bool acc) {
    uint32_t en = acc ? 1u : 0u, z = 0u;
    asm volatile("{\n\t.reg .pred p;\n\tsetp.ne.u32 p, %5, 0;\n\t"
        "tcgen05.mma.cta_group::1.kind::f16 [%0], %1, %2, %3, {%4,%4,%4,%4}, p;\n\t}"
        :: "r"(d), "l"(ad), "l"(bd), "r"(idesc), "r"(z), "r"(en) : "memory");
}
// cg2: M=256 across the pair; 8-reg disable vector; leader (rank 0) issues only
__device__ __forceinline__ void mma_f16_cg2(uint32_t d, uint64_t ad, uint64_t bd, uint32_t idesc, bool acc) {
    uint32_t en = acc ? 1u : 0u;
    asm volatile("{\n\t.reg .pred p;\n\tsetp.ne.u32 p, %6, 0;\n\t"
        "tcgen05.mma.cta_group::2.kind::f16 [%0], %1, %2, %3, {%4,%4,%4,%4,%4,%4,%4,%4}, p;\n\t}"
        :: "r"(d), "l"(ad), "l"(bd), "r"(idesc), "r"(0u), "r"(0u), "r"(en) : "memory");
}
#endif // TC_OK

static __device__ __forceinline__ uint64_t make_desc(uint32_t addr) {
    // K-major SW128: layout=2, version=1, SBO=64, LBO=1
    uint64_t d = (uint64_t(2) << 61) | (uint64_t(1) << 46) | (uint64_t(64) << 32) | (uint64_t(1) << 16);
    return d | ((uint64_t)(addr >> 4) & 0x3FFF);
}
__device__ __forceinline__ uint32_t sw128(uint32_t o) { return o ^ ((o >> 3) & 0x70); }
__device__ __forceinline__ float gelu_exact(float x) {
    return 0.5f * x * (1.0f + erff(x * 0.7071067811865476f));
}
__device__ __forceinline__ float warp_sum(float v) {
    #pragma unroll
    for (int o = 16; o; o >>= 1) v += __shfl_xor_sync(0xffffffffu, v, o);
    return v;
}

template<bool B> struct OutSel;
template<> struct OutSel<true>  { using T = __half; };
template<> struct OutSel<false> { using T = float;  };

#define SMEM_BYTES 99328
// cg2 layout: [0:4) tmem  [64:88) full[3]  [96:120) empty[3]
// A stage s: 1024 + s*16384 (own 128 rows x 64 k fp16, SW128)
// B stage s: 50176 + s*16384 (own N/2 = 128 rows x 64 k fp16, SW128)
#define A2_OFF(s) (1024u  + (uint32_t)(s) * 16384u)
#define B2_OFF(s) (50176u + (uint32_t)(s) * 16384u)
#define STAGE_TX2 65536u   // (A 16K + B 16K) x 2 CTAs

#define IDESC_F16     ((1u << 4) | ((256u / 8) << 17) | ((128u / 16) << 24))
#define IDESC_F16_CG2 ((1u << 4) | ((256u / 8) << 17) | ((256u / 16) << 24))

// ====== cg2 TMA GEMM: x-pair computes 256(M) x 256(N); 3-stage, occ 2 ==========
// Grid: x = M-tiles (pairs along x, matching the validated examples), y = N-tiles.
// EPI: 0 = half(gelu(acc+bias)), 1 = acc+bias+res (float), 2 = acc+bias (float)
template<int EPI, bool EXPERT>
__global__ void __launch_bounds__(256, 2) __cluster_dims__(2, 1, 1)
tma_gemm2(const __grid_constant__ CUtensorMap mA,
          const __grid_constant__ CUtensorMap mB,
          void* __restrict__ C0v, int ldc, long strideC,
          const float* __restrict__ bias0, int strideBias,
          const float* __restrict__ res,
          const int* __restrict__ cnt, int M0, int K) {
#if !TC_OK
    return;
#else
    using CT = typename OutSel<EPI == 0>::T;
    int e = EXPERT ? blockIdx.z : 0;
    int M = EXPERT ? cnt[e] : M0;
    int pairBase = (blockIdx.x & ~1) * 128;
    if (pairBase >= M) return;               // pair-consistent exit
    int rank = blockIdx.x & 1;
    int mBase = blockIdx.x * 128;            // this CTA's rows
    int colBase = blockIdx.y * 256;

    extern __shared__ char smem[];
    uint32_t sb = smem_u32(smem);
    int tid = threadIdx.x, wid = tid >> 5, lane = tid & 31;

    if (wid == 0) { TCGEN05_ALLOC_CG2(sb, 256); TCGEN05_RELINQ_CG2(); }
    if (tid == 0) {
        #pragma unroll
        for (int s = 0; s < 3; s++) { MBARRIER_INIT(sb + 64 + s * 8, 1); MBARRIER_INIT(sb + 96 + s * 8, 1); }
    }
    __syncthreads();
    CLUSTER_SYNC();    // peer TMA/commit must not hit uninitialized barriers
    uint32_t tmem;
    asm volatile("ld.shared.b32 %0, [%1];" : "=r"(tmem) : "r"(sb));

    CT* C = (CT*)C0v + (EXPERT ? (long)e * strideC : 0);
    const float* bias = bias0 + (EXPERT ? e * strideBias : 0);

    uint64_t aDesc[3], bDesc[3];
    #pragma unroll
    for (int s = 0; s < 3; s++) { aDesc[s] = make_desc(sb + A2_OFF(s)); bDesc[s] = make_desc(sb + B2_OFF(s)); }

    int T = K / 64;
    int bColBase = colBase + rank * 128;     // each CTA loads its N/2 B rows

    if (wid == 0) {
        bool lead = elect_one_pred() != 0;
        bool isL = (rank == 0);
        if (lead) {
            #pragma unroll
            for (int s = 0; s < 3; s++) {
                if (isL) MBARRIER_EXPECT_TX(sb + 64 + s * 8, STAGE_TX2);
                TMA_LOAD_3D_CG2(sb + A2_OFF(s), &mA, s * 64, mBase,    e, sb + 64 + s * 8);
                TMA_LOAD_3D_CG2(sb + B2_OFF(s), &mB, s * 64, bColBase, e, sb + 64 + s * 8);
            }
        }
        uint32_t phF = 0, phE = 0;
        int b = 0;
        for (int t = 0; t < T; t++) {
            if (isL) {
                MBARRIER_WAIT_PARITY(sb + 64 + b * 8, (phF >> b) & 1); phF ^= 1u << b;
                if (lead) {
                    #pragma unroll
                    for (int k = 0; k < 4; k++)
                        mma_f16_cg2(tmem, aDesc[b] + k * 2, bDesc[b] + k * 2, IDESC_F16_CG2, (t > 0) || (k > 0));
                    TCGEN05_COMMIT_MC_CG2(sb + 96 + b * 8, 0x3);
                }
            }
            if (t + 3 < T) {
                // buffer b is reused for stage t+3 — wait its MMA drained first
                MBARRIER_WAIT_PARITY(sb + 96 + b * 8, (phE >> b) & 1); phE ^= 1u << b;
                if (lead) {
                    int kx = (t + 3) * 64;
                    if (isL) MBARRIER_EXPECT_TX(sb + 64 + b * 8, STAGE_TX2);
                    TMA_LOAD_3D_CG2(sb + A2_OFF(b), &mA, kx, mBase,    e, sb + 64 + b * 8);
                    TMA_LOAD_3D_CG2(sb + B2_OFF(b), &mB, kx, bColBase, e, sb + 64 + b * 8);
                }
            }
            if (++b == 3) b = 0;
        }
        // final commit is last in-order -> one wait covers all MMAs
        int lb = (T - 1) % 3;
        MBARRIER_WAIT_PARITY(sb + 96 + lb * 8, (phE >> lb) & 1);
    }
    __syncthreads();
    TCGEN05_FENCE_AFTER();

    // --- epilogue: each CTA drains its own 128 rows from its own TMEM ---
    int wq = wid & 3, wh = wid >> 2;
    int row = mBase + wq * 32 + lane;
    bool rOk = row < M;
    CT* crow = C + (long)row * ldc;
    const float* rrow = res + (long)row * ldc;
    #pragma unroll
    for (int c = 0; c < 4; c++) {
        int col0 = wh * 128 + c * 32;
        uint32_t r[32];
        TCGEN05_LD_X32(r, tmem + col0);
        TCGEN05_WAIT_LD();
        if (rOk) {
            #pragma unroll
            for (int j = 0; j < 32; j += 4) {
                int g = colBase + col0 + j;
                float4 o;
                o.x = __uint_as_float(r[j + 0]) + bias[g + 0];
                o.y = __uint_as_float(r[j + 1]) + bias[g + 1];
                o.z = __uint_as_float(r[j + 2]) + bias[g + 2];
                o.w = __uint_as_float(r[j + 3]) + bias[g + 3];
                if (EPI == 0) {
                    __half2 h0 = __floats2half2_rn(gelu_exact(o.x), gelu_exact(o.y));
                    __half2 h1v = __floats2half2_rn(gelu_exact(o.z), gelu_exact(o.w));
                    __half2* hp = (__half2*)((__half*)crow + g);
                    hp[0] = h0; hp[1] = h1v;
                } else {
                    if (EPI == 1) {
                        o.x += rrow[g + 0]; o.y += rrow[g + 1];
                        o.z += rrow[g + 2]; o.w += rrow[g + 3];
                    }
                    *(float4*)((float*)crow + g) = o;
                }
            }
        }
    }
    TCGEN05_FENCE_BEFORE();
    __syncthreads();
    if (wid == 0) { TCGEN05_DEALLOC_CG2(tmem, 256); }
    CLUSTER_SYNC();   // no CTA exits while pair traffic may be in flight
#endif // TC_OK
}

// ============ cp.async-fed gather GEMM (expert GEMM1), 2-stage (R11-proven) ====
__global__ void __launch_bounds__(256, 2)
gather_gemm(const __half* __restrict__ A0, int lda,
            const __half* __restrict__ B0, int ldb, long strideB,
            __half* __restrict__ C0, int ldc, long strideC,
            const float* __restrict__ bias0, int strideBias,
            const int* __restrict__ tok, int tokStride,
            const int* __restrict__ cnt, int K) {
#if !TC_OK
    return;
#else
    int e = blockIdx.z;
    int M = cnt[e];
    int mBase = blockIdx.y * 128;
    if (mBase >= M) return;
    int colBase = blockIdx.x * 256;

    extern __shared__ char smem[];
    uint32_t sb = smem_u32(smem);
    int tid = threadIdx.x, wid = tid >> 5, lane = tid & 31;

    if (wid == 0) { TCGEN05_ALLOC(sb, 256); TCGEN05_RELINQ(); }
    if (tid == 0) { MBARRIER_INIT(sb + 8, 1); MBARRIER_INIT(sb + 16, 1); }
    __syncthreads();
    uint32_t tmem;
    asm volatile("ld.shared.b32 %0, [%1];" : "=r"(tmem) : "r"(sb));

    const __half* B = B0 + (long)e * strideB;
    __half*       C = C0 + (long)e * strideC;
    const float* bias = bias0 + e * strideBias;

    const __half* aPtr[4]; uint32_t aSz[4]; uint32_t aSoff[4];
    #pragma unroll
    for (int i = 0; i < 4; i++) {
        int idx = tid + 256 * i;
        int r = idx >> 3, kq = idx & 7;
        int grow = mBase + r;
        bool ok = grow < M;
        long rr = ok ? (long)tok[e * tokStride + grow] : 0;
        aPtr[i] = A0 + rr * (long)lda + kq * 8;
        aSz[i] = ok ? 16u : 0u;
        aSoff[i] = sw128((uint32_t)(r * 128 + kq * 16));
    }
    const __half* bPtr[8]; uint32_t bSoff[8];
    #pragma unroll
    for (int i = 0; i < 8; i++) {
        int idx = tid + 256 * i;
        int r = idx >> 3, kq = idx & 7;
        bPtr[i] = B + (long)(colBase + r) * ldb + kq * 8;
        bSoff[i] = sw128((uint32_t)(r * 128 + kq * 16));
    }

    const uint32_t aOff[2] = { 1024u, 1024u + 16384u };
    const uint32_t bOff[2] = { 33792u, 33792u + 32768u };
    uint64_t aDesc[2], bDesc[2];
    #pragma unroll
    for (int s = 0; s < 2; s++) { aDesc[s] = make_desc(sb + aOff[s]); bDesc[s] = make_desc(sb + bOff[s]); }

    #pragma unroll
    for (int i = 0; i < 4; i++) cpa16(sb + aOff[0] + aSoff[i], aPtr[i], aSz[i]);
    #pragma unroll
    for (int i = 0; i < 8; i++) cpa16(sb + bOff[0] + bSoff[i], bPtr[i], 16u);
    CP_COMMIT();

    int T = K / 64;
    int ph0 = 0, ph1 = 0;
    for (int t = 0; t < T; t++) {
        int b = t & 1;
        if (t + 1 < T) {
            int s = b ^ 1;
            if (t >= 1) {
                if (s) { MBARRIER_WAIT_PARITY(sb + 16, ph1); ph1 ^= 1; }
                else   { MBARRIER_WAIT_PARITY(sb + 8,  ph0); ph0 ^= 1; }
            }
            int off = (t + 1) * 64;
            #pragma unroll
            for (int i = 0; i < 4; i++) cpa16(sb + aOff[s] + aSoff[i], aPtr[i] + off, aSz[i]);
            #pragma unroll
            for (int i = 0; i < 8; i++) cpa16(sb + bOff[s] + bSoff[i], bPtr[i] + off, 16u);
            CP_COMMIT();
            CP_WAIT1();
        } else {
            CP_WAIT0();
        }
        asm volatile("fence.proxy.async.shared::cta;" ::: "memory");
        __syncthreads();
        if (wid == 0 && elect_one_pred()) {
            #pragma unroll
            for (int k = 0; k < 4; k++)
                mma_f16(tmem, aDesc[b] + k * 2, bDesc[b] + k * 2, IDESC_F16, (t > 0) || (k > 0));
            TCGEN05_COMMIT(sb + 8 + b * 8);
        }
    }
    {
        int lb = (T - 1) & 1;
        if (lb) { MBARRIER_WAIT_PARITY(sb + 16, ph1); }
        else    { MBARRIER_WAIT_PARITY(sb + 8,  ph0); }
    }
    TCGEN05_FENCE_AFTER();

    int wq = wid & 3, wh = wid >> 2;
    int row = mBase + wq * 32 + lane;
    bool rOk = row < M;
    __half* crow = C + (long)row * ldc;
    #pragma unroll
    for (int c = 0; c < 4; c++) {
        int col0 = wh * 128 + c * 32;
        uint32_t r[32];
        TCGEN05_LD_X32(r, tmem + col0);
        TCGEN05_WAIT_LD();
        if (rOk) {
            #pragma unroll
            for (int j = 0; j < 32; j += 4) {
                int g = colBase + col0 + j;
                float vx = __uint_as_float(r[j + 0]) + bias[g + 0];
                float vy = __uint_as_float(r[j + 1]) + bias[g + 1];
                float vz = __uint_as_float(r[j + 2]) + bias[g + 2];
                float vw = __uint_as_float(r[j + 3]) + bias[g + 3];
                __half2* hp = (__half2*)(crow + g);
                hp[0] = __floats2half2_rn(gelu_exact(vx), gelu_exact(vy));
                hp[1] = __floats2half2_rn(gelu_exact(vz), gelu_exact(vw));
            }
        }
    }
    TCGEN05_FENCE_BEFORE();
    __syncthreads();
    if (wid == 0) TCGEN05_DEALLOC(tmem, 256);
#endif // TC_OK
}

// ---------------- fused weight transpose (also resets cnt) ----------------
__global__ void transpose_all(const float* __restrict__ w1, __half* __restrict__ w1t,
                              const float* __restrict__ w2, __half* __restrict__ w2t,
                              const float* __restrict__ e1, __half* __restrict__ e1t,
                              const float* __restrict__ e2, __half* __restrict__ e2t,
                              int* __restrict__ cnt) {
    if (blockIdx.x == 0 && threadIdx.x < NEXP) cnt[threadIdx.x] = 0;
    int id = blockIdx.x;
    const float* in; __half* outp; int R, C;
    if (id < 4096)        { in = w1; outp = w1t; R = H;    C = MLPH; }
    else if (id < 8192)   { id -= 4096; in = w2; outp = w2t; R = MLPH; C = H; }
    else if (id < 24576)  { id -= 8192; int ex = id >> 11; id &= 2047;
                            in = e1 + (size_t)ex * H * EXPH; outp = e1t + (size_t)ex * H * EXPH;
                            R = H; C = EXPH; }
    else                  { id -= 24576; int ex = id >> 11; id &= 2047;
                            in = e2 + (size_t)ex * EXPH * H; outp = e2t + (size_t)ex * EXPH * H;
                            R = EXPH; C = H; }
    int ctiles = C >> 5;
    int r0 = (id / ctiles) << 5, c0 = (id % ctiles) << 5;

    __shared__ float tile[32][33];
    int tid = threadIdx.x;
    int row = tid >> 3, q = tid & 7;
    float4 v = *(const float4*)&in[(size_t)(r0 + row) * C + c0 + q * 4];
    tile[row][q * 4 + 0] = v.x; tile[row][q * 4 + 1] = v.y;
    tile[row][q * 4 + 2] = v.z; tile[row][q * 4 + 3] = v.w;
    __syncthreads();
    int h2 = tid & 15, ccb = tid >> 4;
    #pragma unroll
    for (int p = 0; p < 2; p++) {
        int cc = ccb + p * 16;
        __half2 hv = __floats2half2_rn(tile[h2 * 2][cc], tile[h2 * 2 + 1][cc]);
        *(__half2*)&outp[(size_t)(c0 + cc) * R + r0 + h2 * 2] = hv;
    }
}

// ---------------- warp-per-token LayerNorm (+optional fused router) ------------
template<int ADDSELF, int DOROUTER>
__global__ void __launch_bounds__(128)
ln_warp(const float* __restrict__ in, const float* __restrict__ g,
        const float* __restrict__ b, __half* __restrict__ outH,
        const float* __restrict__ rw, int* __restrict__ cnt,
        int* __restrict__ tok, int* __restrict__ slot,
        float* __restrict__ wgt, int NT) {
    int warp = threadIdx.x >> 5, lane = threadIdx.x & 31;
    int n = blockIdx.x * 4 + warp;
    const float4* inr = (const float4*)(in + (long)n * H);
    const float4* g4  = (const float4*)g;
    const float4* b4  = (const float4*)b;

    float4 v[8];
    float s = 0.f;
    #pragma unroll
    for (int j = 0; j < 8; j++) {
        v[j] = inr[j * 32 + lane];
        s += v[j].x + v[j].y + v[j].z + v[j].w;
    }
    float mean = warp_sum(s) * (1.0f / H);
    float vs = 0.f;
    #pragma unroll
    for (int j = 0; j < 8; j++) {
        float dx = v[j].x - mean, dy = v[j].y - mean, dz = v[j].z - mean, dw = v[j].w - mean;
        vs += dx * dx + dy * dy + dz * dz + dw * dw;
    }
    float rs = rsqrtf(warp_sum(vs) * (1.0f / H) + 1e-5f);

    __half* outRow = outH + (long)n * H;
    #pragma unroll
    for (int j = 0; j < 8; j++) {
        int idx = j * 32 + lane;
        float4 gv = g4[idx], bv = b4[idx];
        float4 o;
        o.x = (v[j].x - mean) * rs * gv.x + bv.x;
        o.y = (v[j].y - mean) * rs * gv.y + bv.y;
        o.z = (v[j].z - mean) * rs * gv.z + bv.z;
        o.w = (v[j].w - mean) * rs * gv.w + bv.w;
        if (ADDSELF) { o.x += v[j].x; o.y += v[j].y; o.z += v[j].z; o.w += v[j].w; }
        v[j] = o;   // keep fp32 for router
        __half2 h01 = __floats2half2_rn(o.x, o.y);
        __half2 h23 = __floats2half2_rn(o.z, o.w);
        uint2 u = make_uint2(*(unsigned*)&h01, *(unsigned*)&h23);
        *(uint2*)(outRow + idx * 4) = u;
    }

    if (DOROUTER) {
        float acc[NEXP];
        #pragma unroll
        for (int e = 0; e < NEXP; e++) acc[e] = 0.f;
        #pragma unroll
        for (int j = 0; j < 8; j++) {
            int h0 = (j * 32 + lane) * 4;
            float xv[4] = { v[j].x, v[j].y, v[j].z, v[j].w };
            #pragma unroll
            for (int k = 0; k < 4; k++) {
                const float4* r = (const float4*)&rw[(h0 + k) * NEXP];
                float4 r0 = r[0], r1 = r[1];
                float x = xv[k];
                acc[0] += x * r0.x; acc[1] += x * r0.y; acc[2] += x * r0.z; acc[3] += x * r0.w;
                acc[4] += x * r1.x; acc[5] += x * r1.y; acc[6] += x * r1.z; acc[7] += x * r1.w;
            }
        }
        #pragma unroll
        for (int e = 0; e < NEXP; e++) acc[e] = warp_sum(acc[e]);
        if (lane == 0) {
            int i1 = 0;
            #pragma unroll
            for (int e = 1; e < NEXP; e++) if (acc[e] > acc[i1]) i1 = e;
            int i2 = (i1 == 0) ? 1 : 0;
            #pragma unroll
            for (int e = 0; e < NEXP; e++) { if (e == i1 || e == i2) continue; if (acc[e] > acc[i2]) i2 = e; }
            float d  = expf(acc[i2] - acc[i1]);
            float w1 = 1.0f / (1.0f + d);
            float w2 = d / (1.0f + d);
            int p1 = atomicAdd(&cnt[i1], 1);
            int p2 = atomicAdd(&cnt[i2], 1);
            tok[i1 * NT + p1] = n;
            tok[i2 * NT + p2] = n;
            slot[2*n]   = i1 * NT + p1;  wgt[2*n]   = w1;
            slot[2*n+1] = i2 * NT + p2;  wgt[2*n+1] = w2;
        }
    }
}

// ---------------- warp-per-token combine + final LN ----------------
__global__ void __launch_bounds__(128)
combine_ln_warp(const float* __restrict__ ye, const int* __restrict__ slot,
                const float* __restrict__ wgt, const float* __restrict__ g,
                const float* __restrict__ b, float* __restrict__ out) {
    int warp = threadIdx.x >> 5, lane = threadIdx.x & 31;
    int n = blockIdx.x * 4 + warp;
    int s0 = slot[2*n], s1 = slot[2*n+1];
    float w0 = wgt[2*n], w1 = wgt[2*n+1];
    const float4* y0r = (const float4*)(ye + (long)s0 * H);
    const float4* y1r = (const float4*)(ye + (long)s1 * H);
    const float4* g4  = (const float4*)g;
    const float4* b4  = (const float4*)b;

    float4 v[8];
    float s = 0.f;
    #pragma unroll
    for (int j = 0; j < 8; j++) {
        int idx = j * 32 + lane;
        float4 y0 = y0r[idx], y1 = y1r[idx];
        float4 t;
        t.x = w0 * y0.x + w1 * y1.x;
        t.y = w0 * y0.y + w1 * y1.y;
        t.z = w0 * y0.z + w1 * y1.z;
        t.w = w0 * y0.w + w1 * y1.w;
        v[j] = t;
        s += t.x + t.y + t.z + t.w;
    }
    float mean = warp_sum(s) * (1.0f / H);
    float vs = 0.f;
    #pragma unroll
    for (int j = 0; j < 8; j++) {
        float dx = v[j].x - mean, dy = v[j].y - mean, dz = v[j].z - mean, dw = v[j].w - mean;
        vs += dx * dx + dy * dy + dz * dz + dw * dw;
    }
    float rs = rsqrtf(warp_sum(vs) * (1.0f / H) + 1e-5f);

    float4* outRow = (float4*)(out + (long)n * H);
    #pragma unroll
    for (int j = 0; j < 8; j++) {
        int idx = j * 32 + lane;
        float4 gv = g4[idx], bv = b4[idx];
        float4 o;
        o.x = (v[j].x - mean) * rs * gv.x + bv.x;
        o.y = (v[j].y - mean) * rs * gv.y + bv.y;
        o.z = (v[j].z - mean) * rs * gv.z + bv.z;
        o.w = (v[j].w - mean) * rs * gv.w + bv.w;
        outRow[idx] = o;
    }
}

__global__ void aux_kernel(const int* __restrict__ cnt, float* __restrict__ out,
                           long auxIdx, float invTotal) {
    float a = 0.f;
    #pragma unroll
    for (int e = 0; e < NEXP; e++) {
        float load = (float)cnt[e] * invTotal;
        a += load * logf(load + 1e-9f);
    }
    out[auxIdx] = 0.01f * a;
}

// ---------------- host: tensormap builder via dlopen ----------------
typedef CUresult (*EncodeFn)(CUtensorMap*, CUtensorMapDataType, cuuint32_t, void*,
                             const cuuint64_t*, const cuuint64_t*, const cuuint32_t*,
                             const cuuint32_t*, CUtensorMapInterleave, CUtensorMapSwizzle,
                             CUtensorMapL2promotion, CUtensorMapFloatOOBfill);

static void make_map_h(EncodeFn enc, CUtensorMap* m, void* ptr,
                       uint64_t d0, uint64_t d1, uint64_t d2, uint32_t box1) {
    cuuint64_t dims[3]    = { d0, d1, d2 };
    cuuint64_t strides[2] = { d0 * 2, d0 * d1 * 2 };
    cuuint32_t box[3]     = { 64u, box1, 1u };
    cuuint32_t es[3]      = { 1u, 1u, 1u };
    enc(m, CU_TENSOR_MAP_DATA_TYPE_FLOAT16, 3, ptr, dims, strides, box, es,
        CU_TENSOR_MAP_INTERLEAVE_NONE, CU_TENSOR_MAP_SWIZZLE_128B,
        CU_TENSOR_MAP_L2_PROMOTION_L2_128B, CU_TENSOR_MAP_FLOAT_OOB_FILL_NONE);
}

// ---------------- launch ----------------
extern "C" void kernel_launch(void* const* d_in, const int* in_sizes, int n_in,
                              void* d_out, int out_size) {
    const float* x    = (const float*)d_in[0];
    const float* ln1g = (const float*)d_in[1];
    const float* ln1b = (const float*)d_in[2];
    const float* ln2g = (const float*)d_in[3];
    const float* ln2b = (const float*)d_in[4];
    const float* w1   = (const float*)d_in[5];
    const float* b1   = (const float*)d_in[6];
    const float* w2   = (const float*)d_in[7];
    const float* b2   = (const float*)d_in[8];
    const float* rw   = (const float*)d_in[9];
    const float* ew1  = (const float*)d_in[10];
    const float* eb1  = (const float*)d_in[11];
    const float* ew2  = (const float*)d_in[12];
    const float* eb2  = (const float*)d_in[13];
    const float* lnfg = (const float*)d_in[14];
    const float* lnfb = (const float*)d_in[15];
    float* out = (float*)d_out;

    int NT = in_sizes[0] / H;   // 4096

    __half *xn, *h1, *x2h, *he, *w1t, *w2t, *e1t, *e2t;
    float *hh, *ye, *wgt;
    int *cnt, *tok, *slot;
    cudaGetSymbolAddress((void**)&xn,   g_xn);
    cudaGetSymbolAddress((void**)&h1,   g_h1);
    cudaGetSymbolAddress((void**)&hh,   g_h);
    cudaGetSymbolAddress((void**)&x2h,  g_x2h);
    cudaGetSymbolAddress((void**)&he,   g_he);
    cudaGetSymbolAddress((void**)&ye,   g_ye);
    cudaGetSymbolAddress((void**)&wgt,  g_wgt);
    cudaGetSymbolAddress((void**)&cnt,  g_cnt);
    cudaGetSymbolAddress((void**)&tok,  g_tok);
    cudaGetSymbolAddress((void**)&slot, g_slot);
    cudaGetSymbolAddress((void**)&w1t,  g_w1t);
    cudaGetSymbolAddress((void**)&w2t,  g_w2t);
    cudaGetSymbolAddress((void**)&e1t,  g_e1t);
    cudaGetSymbolAddress((void**)&e2t,  g_e2t);

    // tensormaps (host-built; deterministic; baked into graph as kernel params)
    void* hcu = dlopen("libcuda.so.1", RTLD_LAZY | RTLD_GLOBAL);
    if (!hcu) hcu = dlopen("libcuda.so", RTLD_LAZY | RTLD_GLOBAL);
    EncodeFn enc = hcu ? (EncodeFn)dlsym(hcu, "cuTensorMapEncodeTiled") : nullptr;
    CUtensorMap mXn, mW1, mH1, mW2, mHe, mE2;
    make_map_h(enc, &mXn, xn,  H,    (uint64_t)NT, 1,    128);
    make_map_h(enc, &mW1, w1t, H,    MLPH,         1,    128);  // cg2: 128-row B slices
    make_map_h(enc, &mH1, h1,  MLPH, (uint64_t)NT, 1,    128);
    make_map_h(enc, &mW2, w2t, MLPH, H,            1,    128);
    make_map_h(enc, &mHe, he,  EXPH, (uint64_t)NT, NEXP, 128);
    make_map_h(enc, &mE2, e2t, EXPH, H,            NEXP, 128);

    cudaFuncSetAttribute(tma_gemm2<0, false>, cudaFuncAttributeMaxDynamicSharedMemorySize, SMEM_BYTES);
    cudaFuncSetAttribute(tma_gemm2<1, false>, cudaFuncAttributeMaxDynamicSharedMemorySize, SMEM_BYTES);
    cudaFuncSetAttribute(tma_gemm2<2, true >, cudaFuncAttributeMaxDynamicSharedMemorySize, SMEM_BYTES);
    cudaFuncSetAttribute(gather_gemm,         cudaFuncAttributeMaxDynamicSharedMemorySize, SMEM_BYTES);

    // fused weight transpose + fp16 convert (+cnt reset) — ONE launch
    transpose_all<<<40960, 256>>>(w1, w1t, w2, w2t, ew1, e1t, ew2, e2t, cnt);

    // ResMLP block (cg2 pair GEMMs: pairs along x = M tiles, per the examples)
    ln_warp<0, 0><<<NT / 4, 128>>>(x, ln1g, ln1b, xn,
                                   nullptr, nullptr, nullptr, nullptr, nullptr, NT);
    tma_gemm2<0, false><<<dim3(NT/128, MLPH/256), 256, SMEM_BYTES>>>(
        mXn, mW1, h1, MLPH, 0, b1, 0, nullptr, nullptr, NT, H);
    tma_gemm2<1, false><<<dim3(NT/128, H/256), 256, SMEM_BYTES>>>(
        mH1, mW2, hh, H, 0, b2, 0, x, nullptr, NT, MLPH);

    // LN2 + fused router (exact fp32 logits from registers)
    ln_warp<1, 1><<<NT / 4, 128>>>(hh, ln2g, ln2b, x2h,
                                   rw, cnt, tok, slot, wgt, NT);

    // MoE
    gather_gemm<<<dim3(EXPH/256, NT/128, NEXP), 256, SMEM_BYTES>>>(
        x2h, H,  e1t, H, (long)EXPH * H,  he, EXPH, (long)NT * EXPH,
        eb1, EXPH, tok, NT, cnt, H);
    tma_gemm2<2, true><<<dim3(NT/128, H/256, NEXP), 256, SMEM_BYTES>>>(
        mHe, mE2, ye, H, (long)NT * H, eb2, H, nullptr, cnt, NT, EXPH);

    // combine + final LN + aux
    combine_ln_warp<<<NT / 4, 128>>>(ye, slot, wgt, lnfg, lnfb, out);
    if (out_size > NT * H)
        aux_kernel<<<1, 1>>>(cnt, out, (long)NT * H, 1.0f / (2.0f * NT));
}